// round 16
// baseline (speedup 1.0000x reference)
#include <cuda_runtime.h>

// MSD block: 12 dilated 3x3 convs (reflect pad, ReLU), channels concatenated.
// d_out holds the (4, 25, 512, 512) concat tensor; layer i reads channels
// [0, n_in) and writes [n_in, n_in+2) in place.
//
// Light layers (D<=4): R1 body, R=16.  Small heavy (NIN=9,11): ic-pair body,
// R=32.  Large heavy (NIN>=13): CHANNEL-SPLIT — grid.z=8 (batch x half);
// half A sums ic [0,NH) into a __device__ scratch (acc=0), half B sums
// ic [NH,NIN) + bias into the output channels; a small epilogue computes
// out = max(out + scratch, 0). Doubles warp supply on the biggest layers at
// zero extra per-tap instructions.

#define Bdim 4
#define Hdim 512
#define Wdim 512
#define C_TOTAL 25
#define CS (Hdim * Wdim)

typedef unsigned long long u64;

// 8 MB partial-sum scratch: [batch][oc(2)][512][512]
__device__ float g_scratch[Bdim * 2 * CS];

__device__ __forceinline__ void fma2(u64& d, u64 a, u64 b) {
    asm("fma.rn.f32x2 %0, %1, %2, %0;" : "+l"(d) : "l"(a), "l"(b));
}
__device__ __forceinline__ u64 dup2(float v) {
    u64 r; asm("mov.b64 %0, {%1, %1};" : "=l"(r) : "f"(v)); return r;
}
__device__ __forceinline__ u64 pack2(float lo, float hi) {
    u64 r; asm("mov.b64 %0, {%1, %2};" : "=l"(r) : "f"(lo), "f"(hi)); return r;
}
__device__ __forceinline__ void unpack2(u64 v, float& lo, float& hi) {
    asm("mov.b64 {%0, %1}, %2;" : "=f"(lo), "=f"(hi) : "l"(v));
}

// ======================= LIGHT: R1 body, verbatim ==========================
template<int N_IN, int D, int R, bool REFL>
__device__ __forceinline__ void conv_body(const float* __restrict__ buf,
                                          float* __restrict__ outp,
                                          const u64* __restrict__ ws2,
                                          u64 bias2, int b, int r0, int w) {
    int wl = w - D; if (wl < 0) wl = -wl;
    int wr = w + D; if (wr >= Wdim) wr = 2 * Wdim - 2 - wr;

    u64 acc[R];
    #pragma unroll
    for (int m = 0; m < R; ++m) acc[m] = bias2;

    #pragma unroll 1
    for (int ic = 0; ic < N_IN; ++ic) {
        const float* plane = buf + ((size_t)b * C_TOTAL + ic) * CS;
        const u64* wrow = ws2 + ic * 9;
        u64 w00 = wrow[0], w01 = wrow[1], w02 = wrow[2];
        u64 w10 = wrow[3], w11 = wrow[4], w12 = wrow[5];
        u64 w20 = wrow[6], w21 = wrow[7], w22 = wrow[8];
        #pragma unroll
        for (int j = 0; j < R + 2 * D; ++j) {
            int x = r0 - D + j;
            int xr = x;
            if (REFL) {
                if (x < 0) xr = -x;
                else if (x >= Hdim) xr = 2 * Hdim - 2 - x;
            }
            const float* row = plane + (size_t)xr * Wdim;
            u64 vl = dup2(__ldg(row + wl));
            u64 vc = dup2(__ldg(row + w));
            u64 vr = dup2(__ldg(row + wr));
            if (j < R) {
                fma2(acc[j], w00, vl); fma2(acc[j], w01, vc); fma2(acc[j], w02, vr);
            }
            if (j >= D && j < R + D) {
                fma2(acc[j - D], w10, vl); fma2(acc[j - D], w11, vc); fma2(acc[j - D], w12, vr);
            }
            if (j >= 2 * D) {
                fma2(acc[j - 2 * D], w20, vl); fma2(acc[j - 2 * D], w21, vc); fma2(acc[j - 2 * D], w22, vr);
            }
        }
    }

    float* o0 = outp + ((size_t)b * C_TOTAL + N_IN) * CS + (size_t)r0 * Wdim + w;
    #pragma unroll
    for (int m = 0; m < R; ++m) {
        float lo, hi; unpack2(acc[m], lo, hi);
        o0[(size_t)m * Wdim]      = fmaxf(lo, 0.f);
        o0[CS + (size_t)m * Wdim] = fmaxf(hi, 0.f);
    }
}

template<int N_IN, int D, int R>
__global__ __launch_bounds__(128)
void conv_layer(const float* __restrict__ buf, float* __restrict__ outp,
                const float* __restrict__ wgt, const float* __restrict__ bias,
                int layer) {
    __shared__ u64 ws2[N_IN * 9];
    __shared__ u64 bsh;
    int tid = threadIdx.x;
    for (int i = tid; i < N_IN * 9; i += 128)
        ws2[i] = pack2(wgt[i], wgt[N_IN * 9 + i]);
    if (tid == 0) bsh = pack2(bias[2 * layer], bias[2 * layer + 1]);
    __syncthreads();

    int w  = blockIdx.x * 128 + tid;
    int r0 = blockIdx.y * R;
    int b  = blockIdx.z;
    u64 bias2 = bsh;

    bool interior = (r0 >= D) && (r0 + R + D <= Hdim);
    if (interior) conv_body<N_IN, D, R, false>(buf, outp, ws2, bias2, b, r0, w);
    else          conv_body<N_IN, D, R, true >(buf, outp, ws2, bias2, b, r0, w);
}

// ====== generic ic-range pair body: acc over [IC0,IC1), optional targets =====
// TO_SCRATCH: raw partials -> g_scratch (no bias, no ReLU).
// !TO_SCRATCH && RELU: final store with ReLU (unsplit heavy layers).
// !TO_SCRATCH && !RELU: raw store to out channels (split half B; epilogue ReLUs).
template<int N_IN, int IC0, int IC1, int D, int R, bool REFL, bool TO_SCRATCH, bool RELU>
__device__ __forceinline__ void conv_body_range(const float* __restrict__ buf,
                                                float* __restrict__ outp,
                                                const u64* __restrict__ ws2,
                                                u64 acc0, int b, int r0, int w) {
    int wl = w - D; if (wl < 0) wl = -wl;
    int wr = w + D; if (wr >= Wdim) wr = 2 * Wdim - 2 - wr;

    u64 acc[R];
    #pragma unroll
    for (int m = 0; m < R; ++m) acc[m] = acc0;

    const float* base = buf + (size_t)b * C_TOTAL * CS;

    #pragma unroll 1
    for (int ic = IC0; ic + 1 < IC1; ic += 2) {
        const float* p0 = base + (size_t)ic * CS;
        const float* p1 = p0 + CS;
        const u64* w0 = ws2 + ic * 9;
        const u64* w1 = w0 + 9;
        u64 a00 = w0[0], a01 = w0[1], a02 = w0[2];
        u64 a10 = w0[3], a11 = w0[4], a12 = w0[5];
        u64 a20 = w0[6], a21 = w0[7], a22 = w0[8];
        u64 c00 = w1[0], c01 = w1[1], c02 = w1[2];
        u64 c10 = w1[3], c11 = w1[4], c12 = w1[5];
        u64 c20 = w1[6], c21 = w1[7], c22 = w1[8];
        #pragma unroll
        for (int j = 0; j < R + 2 * D; ++j) {
            int x = r0 - D + j;
            int xr = x;
            if (REFL) {
                if (x < 0) xr = -x;
                else if (x >= Hdim) xr = 2 * Hdim - 2 - x;
            }
            const size_t ro = (size_t)xr * Wdim;
            const float* row0 = p0 + ro;
            const float* row1 = p1 + ro;
            float f0l = __ldg(row0 + wl), f0c = __ldg(row0 + w), f0r = __ldg(row0 + wr);
            float f1l = __ldg(row1 + wl), f1c = __ldg(row1 + w), f1r = __ldg(row1 + wr);
            u64 v0l = dup2(f0l), v0c = dup2(f0c), v0r = dup2(f0r);
            u64 v1l = dup2(f1l), v1c = dup2(f1c), v1r = dup2(f1r);
            if (j < R) {
                fma2(acc[j], a00, v0l); fma2(acc[j], a01, v0c); fma2(acc[j], a02, v0r);
                fma2(acc[j], c00, v1l); fma2(acc[j], c01, v1c); fma2(acc[j], c02, v1r);
            }
            if (j >= D && j < R + D) {
                fma2(acc[j - D], a10, v0l); fma2(acc[j - D], a11, v0c); fma2(acc[j - D], a12, v0r);
                fma2(acc[j - D], c10, v1l); fma2(acc[j - D], c11, v1c); fma2(acc[j - D], c12, v1r);
            }
            if (j >= 2 * D) {
                fma2(acc[j - 2*D], a20, v0l); fma2(acc[j - 2*D], a21, v0c); fma2(acc[j - 2*D], a22, v0r);
                fma2(acc[j - 2*D], c20, v1l); fma2(acc[j - 2*D], c21, v1c); fma2(acc[j - 2*D], c22, v1r);
            }
        }
    }

    if ((IC1 - IC0) & 1) {   // tail channel
        const int ic = IC1 - 1;
        const float* plane = base + (size_t)ic * CS;
        const u64* wrow = ws2 + ic * 9;
        u64 w00 = wrow[0], w01 = wrow[1], w02 = wrow[2];
        u64 w10 = wrow[3], w11 = wrow[4], w12 = wrow[5];
        u64 w20 = wrow[6], w21 = wrow[7], w22 = wrow[8];
        #pragma unroll
        for (int j = 0; j < R + 2 * D; ++j) {
            int x = r0 - D + j;
            int xr = x;
            if (REFL) {
                if (x < 0) xr = -x;
                else if (x >= Hdim) xr = 2 * Hdim - 2 - x;
            }
            const float* row = plane + (size_t)xr * Wdim;
            u64 vl = dup2(__ldg(row + wl));
            u64 vc = dup2(__ldg(row + w));
            u64 vr = dup2(__ldg(row + wr));
            if (j < R) {
                fma2(acc[j], w00, vl); fma2(acc[j], w01, vc); fma2(acc[j], w02, vr);
            }
            if (j >= D && j < R + D) {
                fma2(acc[j - D], w10, vl); fma2(acc[j - D], w11, vc); fma2(acc[j - D], w12, vr);
            }
            if (j >= 2 * D) {
                fma2(acc[j - 2 * D], w20, vl); fma2(acc[j - 2 * D], w21, vc); fma2(acc[j - 2 * D], w22, vr);
            }
        }
    }

    float* o0;
    if (TO_SCRATCH) o0 = g_scratch + ((size_t)b * 2) * CS + (size_t)r0 * Wdim + w;
    else            o0 = outp + ((size_t)b * C_TOTAL + N_IN) * CS + (size_t)r0 * Wdim + w;
    #pragma unroll
    for (int m = 0; m < R; ++m) {
        float lo, hi; unpack2(acc[m], lo, hi);
        if (RELU) { lo = fmaxf(lo, 0.f); hi = fmaxf(hi, 0.f); }
        o0[(size_t)m * Wdim]      = lo;
        o0[CS + (size_t)m * Wdim] = hi;
    }
}

// ============== small heavy (unsplit): ic-pair body, ReLU store ============
template<int N_IN, int D, int R>
__global__ __launch_bounds__(128)
void conv_layer_p2(const float* __restrict__ buf, float* __restrict__ outp,
                   const float* __restrict__ wgt, const float* __restrict__ bias,
                   int layer) {
    __shared__ u64 ws2[N_IN * 9];
    __shared__ u64 bsh;
    int tid = threadIdx.x;
    for (int i = tid; i < N_IN * 9; i += 128)
        ws2[i] = pack2(wgt[i], wgt[N_IN * 9 + i]);
    if (tid == 0) bsh = pack2(bias[2 * layer], bias[2 * layer + 1]);
    __syncthreads();

    int w  = blockIdx.x * 128 + tid;
    int r0 = blockIdx.y * R;
    int b  = blockIdx.z;
    u64 bias2 = bsh;

    bool interior = (r0 >= D) && (r0 + R + D <= Hdim);
    if (interior) conv_body_range<N_IN, 0, N_IN, D, R, false, false, true>(buf, outp, ws2, bias2, b, r0, w);
    else          conv_body_range<N_IN, 0, N_IN, D, R, true,  false, true>(buf, outp, ws2, bias2, b, r0, w);
}

// ================= large heavy: channel-split, grid.z = batch*2 ============
template<int N_IN, int NH, int D, int R>
__global__ __launch_bounds__(128)
void conv_layer_split(const float* __restrict__ buf, float* __restrict__ outp,
                      const float* __restrict__ wgt, const float* __restrict__ bias,
                      int layer) {
    __shared__ u64 ws2[N_IN * 9];
    __shared__ u64 bsh;
    int tid = threadIdx.x;
    for (int i = tid; i < N_IN * 9; i += 128)
        ws2[i] = pack2(wgt[i], wgt[N_IN * 9 + i]);
    if (tid == 0) bsh = pack2(bias[2 * layer], bias[2 * layer + 1]);
    __syncthreads();

    int w    = blockIdx.x * 128 + tid;
    int r0   = blockIdx.y * R;
    int b    = blockIdx.z >> 1;
    int half = blockIdx.z & 1;

    bool interior = (r0 >= D) && (r0 + R + D <= Hdim);
    if (half == 0) {   // channels [0, NH) -> scratch, acc starts at 0
        if (interior) conv_body_range<N_IN, 0, NH, D, R, false, true, false>(buf, outp, ws2, 0ull, b, r0, w);
        else          conv_body_range<N_IN, 0, NH, D, R, true,  true, false>(buf, outp, ws2, 0ull, b, r0, w);
    } else {           // channels [NH, N_IN) + bias -> out (raw; epilogue ReLUs)
        u64 bias2 = bsh;
        if (interior) conv_body_range<N_IN, NH, N_IN, D, R, false, false, false>(buf, outp, ws2, bias2, b, r0, w);
        else          conv_body_range<N_IN, NH, N_IN, D, R, true,  false, false>(buf, outp, ws2, bias2, b, r0, w);
    }
}

// Epilogue for split layers: out = max(out + scratch, 0) on the 2 new planes.
__global__ void epilogue_kernel(float* __restrict__ out, int nin) {
    const int P4 = CS / 4;
    int idx = blockIdx.x * blockDim.x + threadIdx.x;     // over Bdim*2*P4
    if (idx >= Bdim * 2 * P4) return;
    int b  = idx / (2 * P4);
    int r  = idx - b * 2 * P4;
    int oc = r / P4;
    int p  = r - oc * P4;
    float4* o = (float4*)out + ((size_t)(b * C_TOTAL + nin + oc)) * P4 + p;
    const float4* s = (const float4*)g_scratch + ((size_t)(b * 2 + oc)) * P4 + p;
    float4 v = *o, sv = *s;
    v.x = fmaxf(v.x + sv.x, 0.f);
    v.y = fmaxf(v.y + sv.y, 0.f);
    v.z = fmaxf(v.z + sv.z, 0.f);
    v.w = fmaxf(v.w + sv.w, 0.f);
    *o = v;
}

// Copy x (4,1,512,512) into channel 0 of the 25-channel output buffer.
__global__ void copy_in_kernel(const float4* __restrict__ x, float4* __restrict__ out) {
    int idx = blockIdx.x * blockDim.x + threadIdx.x;
    const int P4 = CS / 4;
    if (idx >= Bdim * P4) return;
    int b = idx / P4;
    int p = idx - b * P4;
    out[(size_t)b * (C_TOTAL * P4) + p] = x[idx];
}

extern "C" void kernel_launch(void* const* d_in, const int* in_sizes, int n_in,
                              void* d_out, int out_size) {
    const float* x    = (const float*)d_in[0];
    const float* bias = (const float*)d_in[1];
    float* out = (float*)d_out;

    {
        int total4 = Bdim * CS / 4;
        copy_in_kernel<<<(total4 + 255) / 256, 256>>>((const float4*)x, (float4*)out);
    }

    const int EPI_BLOCKS = (Bdim * 2 * (CS / 4) + 255) / 256;

#define LIGHT(i, NIN, DD, RR) \
    conv_layer<NIN, DD, RR><<<dim3(Wdim / 128, Hdim / RR, Bdim), 128>>>( \
        out, out, (const float*)d_in[2 + (i)], bias, (i))
#define HEAVY(i, NIN, DD, RR) \
    conv_layer_p2<NIN, DD, RR><<<dim3(Wdim / 128, Hdim / RR, Bdim), 128>>>( \
        out, out, (const float*)d_in[2 + (i)], bias, (i))
#define SPLIT(i, NIN, NH, DD, RR) \
    conv_layer_split<NIN, NH, DD, RR><<<dim3(Wdim / 128, Hdim / RR, 2 * Bdim), 128>>>( \
        out, out, (const float*)d_in[2 + (i)], bias, (i)); \
    epilogue_kernel<<<EPI_BLOCKS, 256>>>(out, NIN)

    LIGHT(0,  1,  1, 16);
    LIGHT(1,  3,  2, 16);
    LIGHT(2,  5,  3, 16);
    LIGHT(3,  7,  4, 16);
    HEAVY(4,  9,  5, 32);
    HEAVY(5,  11, 6, 32);
    SPLIT(6,  13,  6,  7, 32);
    SPLIT(7,  15,  8,  8, 32);
    SPLIT(8,  17,  8,  9, 32);
    SPLIT(9,  19, 10, 10, 32);
    SPLIT(10, 21, 10, 11, 32);
    SPLIT(11, 23, 12, 12, 32);
#undef LIGHT
#undef HEAVY
#undef SPLIT
}